// round 1
// baseline (speedup 1.0000x reference)
#include <cuda_runtime.h>
#include <math_constants.h>
#include <cstdint>

#define B_   1024
#define L_   50
#define D_   256
#define D2_  512
#define DEG_ 12
#define BL_  (B_ * L_)   // 51200

// ---------------- scratch (device globals; no allocations allowed) ----------
__device__ __align__(16) float g_temb[B_ * D_];       // target_embedding @ wf_w^T + wf_b
__device__ __align__(16) float g_t2[B_ * D_];         // temb @ at_w2 + at_bias
__device__ float g_alpha[B_];
__device__ __align__(16) float g_hidden[(size_t)BL_ * D_];  // 52.4 MB
__device__ float g_scores[BL_];
__device__ float g_attn[BL_];

// ---------------- helpers ----------------------------------------------------
__device__ __forceinline__ float wredsum(float v) {
#pragma unroll
    for (int o = 16; o > 0; o >>= 1) v += __shfl_xor_sync(0xFFFFFFFFu, v, o);
    return v;
}
__device__ __forceinline__ float wredmax(float v) {
#pragma unroll
    for (int o = 16; o > 0; o >>= 1) v = fmaxf(v, __shfl_xor_sync(0xFFFFFFFFu, v, o));
    return v;
}

// packed f32x2 (FFMA2) — ptxas will not auto-fuse; must come from PTX
__device__ __forceinline__ unsigned long long dup2(float x) {
    unsigned long long r;
    asm("mov.b64 %0, {%1, %1};" : "=l"(r) : "f"(x));
    return r;
}
__device__ __forceinline__ void ffma2(unsigned long long& d, unsigned long long a,
                                      unsigned long long b) {
    asm("fma.rn.f32x2 %0, %1, %2, %0;" : "+l"(d) : "l"(a), "l"(b));
}
__device__ __forceinline__ float2 unpk2(unsigned long long v) {
    float2 f;
    asm("mov.b64 {%0, %1}, %2;" : "=f"(f.x), "=f"(f.y) : "l"(v));
    return f;
}

// ---------------- K1: temb[b,d] = sum_k tgt[b,k]*wfw[d,k] + wfb[d] ----------
// grid (128, 8), 256 threads. Block: 8 batch rows x 32 output dims.
__global__ void k_temb(const float* __restrict__ tgt, const float* __restrict__ wfw,
                       const float* __restrict__ wfb) {
    __shared__ __align__(16) float ts[8][512];
    int tid = threadIdx.x;
    int b0 = blockIdx.x * 8;
#pragma unroll
    for (int ii = 0; ii < 4; ii++) {
        int f = ii * 256 + tid;
        int r = f >> 7, k4 = (f & 127) << 2;
        *(float4*)&ts[r][k4] = *(const float4*)&tgt[(size_t)(b0 + r) * D2_ + k4];
    }
    __syncthreads();
    int w = tid >> 5, lane = tid & 31;
#pragma unroll
    for (int dd = 0; dd < 4; dd++) {
        int d = blockIdx.y * 32 + w * 4 + dd;
        float acc[8];
#pragma unroll
        for (int r = 0; r < 8; r++) acc[r] = 0.f;
#pragma unroll
        for (int kc = 0; kc < 4; kc++) {
            int k = kc * 128 + lane * 4;
            float4 wv = *(const float4*)&wfw[(size_t)d * D2_ + k];
#pragma unroll
            for (int r = 0; r < 8; r++) {
                float4 tv = *(const float4*)&ts[r][k];
                acc[r] += wv.x * tv.x + wv.y * tv.y + wv.z * tv.z + wv.w * tv.w;
            }
        }
        float bias = wfb[d];
        float outv = 0.f;
#pragma unroll
        for (int r = 0; r < 8; r++) {
            float s = wredsum(acc[r]);
            if (lane == r) outv = s + bias;
        }
        if (lane < 8) g_temb[(size_t)(b0 + lane) * D_ + d] = outv;
    }
}

// ---------------- K2: t2[b,n] = sum_k temb[b,k]*w2[k,n] + bias[n] -----------
// grid 64, 256 threads. Block: 16 rows x 256 cols, micro 4x4.
__global__ void k_t2(const float* __restrict__ w2, const float* __restrict__ bias) {
    __shared__ __align__(16) float ts[16][256];
    int tid = threadIdx.x;
    int b0 = blockIdx.x * 16;
#pragma unroll
    for (int ii = 0; ii < 4; ii++) {
        int f = ii * 256 + tid;
        int r = f >> 6, k4 = (f & 63) << 2;
        *(float4*)&ts[r][k4] = *(const float4*)&g_temb[(size_t)(b0 + r) * D_ + k4];
    }
    __syncthreads();
    int rg = tid >> 6, nc = tid & 63;
    float acc[4][4];
#pragma unroll
    for (int i = 0; i < 4; i++)
#pragma unroll
        for (int j = 0; j < 4; j++) acc[i][j] = 0.f;
#pragma unroll 4
    for (int k = 0; k < 256; k++) {
        float4 wv = *(const float4*)&w2[(size_t)k * D_ + nc * 4];
#pragma unroll
        for (int i = 0; i < 4; i++) {
            float a = ts[rg * 4 + i][k];
            acc[i][0] += a * wv.x;
            acc[i][1] += a * wv.y;
            acc[i][2] += a * wv.z;
            acc[i][3] += a * wv.w;
        }
    }
    float4 bv = *(const float4*)&bias[nc * 4];
#pragma unroll
    for (int i = 0; i < 4; i++) {
        float4 o;
        o.x = acc[i][0] + bv.x;
        o.y = acc[i][1] + bv.y;
        o.z = acc[i][2] + bv.z;
        o.w = acc[i][3] + bv.w;
        *(float4*)&g_t2[(size_t)(b0 + rg * 4 + i) * D_ + nc * 4] = o;
    }
}

// ---------------- K3: alpha[b] = sigmoid(temb . aw + ab) + 1 ----------------
__global__ void k_alpha(const float* __restrict__ aw, const float* __restrict__ ab) {
    int lane = threadIdx.x & 31;
    int b = blockIdx.x * 8 + (threadIdx.x >> 5);
    const float* t = g_temb + (size_t)b * D_ + lane * 8;
    float s = 0.f;
#pragma unroll
    for (int j = 0; j < 8; j++) s += t[j] * aw[lane * 8 + j];
    s = wredsum(s);
    if (lane == 0) {
        float x = s + ab[0];
        float a = 1.f / (1.f + expf(-x)) + 1.f;
        if (a == 1.f) a = 1.00001f;
        g_alpha[b] = a;
    }
}

// ---------------- K4: hidden[row,:] = 0.5*(emb[it] + sum_j v_j*emb[c_j]) ----
// grid 12800, 256 threads: 4 rows per block, 64 threads (float4) per row.
__global__ void k_hidden(const int* __restrict__ items, const float* __restrict__ emb,
                         const int* __restrict__ cols, const float* __restrict__ vals) {
    int tid = threadIdx.x;
    int row = blockIdx.x * 4 + (tid >> 6);
    int d4 = (tid & 63) << 2;
    int it = __ldg(&items[row]);
    float4 h = *(const float4*)&emb[(size_t)it * D_ + d4];
    int base = it * DEG_;
#pragma unroll
    for (int j = 0; j < DEG_; j++) {
        int c = __ldg(&cols[base + j]);
        float v = __ldg(&vals[base + j]);
        float4 e = *(const float4*)&emb[(size_t)c * D_ + d4];
        h.x += v * e.x;
        h.y += v * e.y;
        h.z += v * e.z;
        h.w += v * e.w;
    }
    h.x *= 0.5f; h.y *= 0.5f; h.z *= 0.5f; h.w *= 0.5f;
    *(float4*)&g_hidden[(size_t)row * D_ + d4] = h;
}

// ---------------- K5: scores = relu(hidden@w1 + t2[b]) . w0 -----------------
// grid 400, 256 threads. Tile 128 rows x 128 cols (2 passes over N=256),
// micro 8x8, packed f32x2 FMA.
#define ROWFMA(i, av)                                                   \
    {                                                                   \
        unsigned long long ad = dup2(av);                               \
        ffma2(acc[i][0], ad, bLo.x);                                    \
        ffma2(acc[i][1], ad, bLo.y);                                    \
        ffma2(acc[i][2], ad, bHi.x);                                    \
        ffma2(acc[i][3], ad, bHi.y);                                    \
    }

__global__ __launch_bounds__(256) void k_scores(const float* __restrict__ w1,
                                                const float* __restrict__ w0) {
    __shared__ __align__(16) float As_t[16][136];  // 544B rows -> 16B aligned
    __shared__ __align__(16) float Bs[16][128];
    __shared__ float w0s[256];
    __shared__ float red[128][17];

    int tid = threadIdx.x;
    int row0 = blockIdx.x * 128;
    w0s[tid] = w0[tid];
    int tr = tid >> 4, tc = tid & 15;

    float sp[8];
#pragma unroll
    for (int i = 0; i < 8; i++) sp[i] = 0.f;

#pragma unroll
    for (int np = 0; np < 2; np++) {
        int n0 = np * 128;
        unsigned long long acc[8][4];
#pragma unroll
        for (int i = 0; i < 8; i++)
#pragma unroll
            for (int j = 0; j < 4; j++) acc[i][j] = 0ull;

        for (int k0 = 0; k0 < 256; k0 += 16) {
            // stage A (transposed)
#pragma unroll
            for (int ii = 0; ii < 2; ii++) {
                int f = ii * 256 + tid;
                int r = f >> 2, kc = (f & 3) << 2;
                float4 v = *(const float4*)&g_hidden[(size_t)(row0 + r) * D_ + k0 + kc];
                As_t[kc + 0][r] = v.x;
                As_t[kc + 1][r] = v.y;
                As_t[kc + 2][r] = v.z;
                As_t[kc + 3][r] = v.w;
            }
            // stage B
#pragma unroll
            for (int ii = 0; ii < 2; ii++) {
                int f = ii * 256 + tid;
                int kk = f >> 5, n4 = (f & 31) << 2;
                *(float4*)&Bs[kk][n4] = *(const float4*)&w1[(size_t)(k0 + kk) * D_ + n0 + n4];
            }
            __syncthreads();
#pragma unroll
            for (int kk = 0; kk < 16; kk++) {
                float4 aLo = *(const float4*)&As_t[kk][tr * 8];
                float4 aHi = *(const float4*)&As_t[kk][tr * 8 + 4];
                ulonglong2 bLo = *(const ulonglong2*)&Bs[kk][tc * 8];
                ulonglong2 bHi = *(const ulonglong2*)&Bs[kk][tc * 8 + 4];
                ROWFMA(0, aLo.x)
                ROWFMA(1, aLo.y)
                ROWFMA(2, aLo.z)
                ROWFMA(3, aLo.w)
                ROWFMA(4, aHi.x)
                ROWFMA(5, aHi.y)
                ROWFMA(6, aHi.z)
                ROWFMA(7, aHi.w)
            }
            __syncthreads();
        }
        // epilogue: + t2, relu, dot with w0
#pragma unroll
        for (int i = 0; i < 8; i++) {
            int grow = row0 + tr * 8 + i;
            int bb = grow / L_;
            const float* t2p = g_t2 + (size_t)bb * D_ + n0 + tc * 8;
#pragma unroll
            for (int jp = 0; jp < 4; jp++) {
                float2 v = unpk2(acc[i][jp]);
                float r0 = fmaxf(v.x + t2p[jp * 2 + 0], 0.f);
                float r1 = fmaxf(v.y + t2p[jp * 2 + 1], 0.f);
                sp[i] += r0 * w0s[n0 + tc * 8 + jp * 2 + 0] +
                         r1 * w0s[n0 + tc * 8 + jp * 2 + 1];
            }
        }
    }
#pragma unroll
    for (int i = 0; i < 8; i++) red[tr * 8 + i][tc] = sp[i];
    __syncthreads();
    if (tid < 128) {
        float s = 0.f;
#pragma unroll
        for (int t = 0; t < 16; t++) s += red[tid][t];
        g_scores[row0 + tid] = s;
    }
}

// ---------------- K6: entmax-bisect over L=50, one warp per batch row -------
__device__ __forceinline__ float pfun(float z, float inv) {
    z = fmaxf(z, 0.f);
    return powf(z, inv);  // powf(0, inv>0) = 0, matching max(z,0)**inv
}

__global__ void k_entmax() {
    int lane = threadIdx.x & 31;
    int b = blockIdx.x * 8 + (threadIdx.x >> 5);
    float alpha = g_alpha[b];
    float am1 = alpha - 1.f;
    float inv = 1.f / am1;
    float Xa0 = g_scores[b * L_ + lane] * am1;
    float Xa1 = (lane < L_ - 32) ? g_scores[b * L_ + 32 + lane] * am1 : -CUDART_INF_F;

    float m = wredmax(fmaxf(Xa0, Xa1));
    float tau_lo = m - 1.f;
    float tau_hi = m - powf(1.f / (float)L_, am1);
    float f_lo = wredsum(pfun(Xa0 - tau_lo, inv) + pfun(Xa1 - tau_lo, inv)) - 1.f;

    float dm = tau_hi - tau_lo;
    float tau_m = tau_lo;
    for (int it = 0; it < 50; it++) {
        dm *= 0.5f;
        tau_m = tau_lo + dm;
        float fm = wredsum(pfun(Xa0 - tau_m, inv) + pfun(Xa1 - tau_m, inv)) - 1.f;
        if (fm * f_lo >= 0.f) tau_lo = tau_m;  // all lanes agree (butterfly sums)
    }
    float p0 = pfun(Xa0 - tau_m, inv);
    float p1 = pfun(Xa1 - tau_m, inv);
    float s = wredsum(p0 + p1);
    g_attn[b * L_ + lane] = p0 / s;
    if (lane < L_ - 32) g_attn[b * L_ + 32 + lane] = p1 / s;
}

// ---------------- K7: c = attn^T hidden; selu; L2-normalize -----------------
__global__ void k_out(float* __restrict__ out) {
    __shared__ float as[64];
    __shared__ float rs[8];
    int tid = threadIdx.x;
    int b = blockIdx.x;
    if (tid < L_) as[tid] = g_attn[b * L_ + tid];
    __syncthreads();
    const float* hp = g_hidden + (size_t)b * L_ * D_ + tid;
    float acc = 0.f;
#pragma unroll
    for (int l = 0; l < L_; l++) acc += as[l] * hp[(size_t)l * D_];
    const float SC = 1.0507009873554805f;
    const float AL = 1.6732632423543772f;
    float v = acc > 0.f ? SC * acc : SC * AL * expm1f(acc);
    float sq = wredsum(v * v);
    if ((tid & 31) == 0) rs[tid >> 5] = sq;
    __syncthreads();
    if (tid < 32) {
        float t = (tid < 8) ? rs[tid] : 0.f;
        t = wredsum(t);
        if (tid == 0) rs[0] = t;
    }
    __syncthreads();
    out[(size_t)b * D_ + tid] = v / sqrtf(rs[0]);
}

// ---------------- launch ------------------------------------------------------
extern "C" void kernel_launch(void* const* d_in, const int* in_sizes, int n_in,
                              void* d_out, int out_size) {
    const int* items = (const int*)d_in[0];
    // d_in[1] inputs_seq, d_in[2] alias_inputs: unused by reference
    const float* tgt = (const float*)d_in[3];
    const float* emb = (const float*)d_in[4];
    // d_in[5] adj_rows: structure is repeat(arange(N), DEG) -> implicit
    const int* acols = (const int*)d_in[6];
    const float* avals = (const float*)d_in[7];
    const float* wfw = (const float*)d_in[8];
    const float* wfb = (const float*)d_in[9];
    const float* aww = (const float*)d_in[10];
    const float* awb = (const float*)d_in[11];
    const float* w0 = (const float*)d_in[12];
    const float* w1 = (const float*)d_in[13];
    const float* w2 = (const float*)d_in[14];
    const float* abias = (const float*)d_in[15];
    float* out = (float*)d_out;

    k_temb<<<dim3(128, 8), 256>>>(tgt, wfw, wfb);
    k_t2<<<64, 256>>>(w2, abias);
    k_alpha<<<128, 256>>>(aww, awb);
    k_hidden<<<12800, 256>>>(items, emb, acols, avals);
    k_scores<<<400, 256>>>(w1, w0);
    k_entmax<<<128, 256>>>();
    k_out<<<1024, 256>>>(out);
}

// round 3
// speedup vs baseline: 1.4989x; 1.4989x over previous
#include <cuda_runtime.h>
#include <cuda_bf16.h>
#include <math_constants.h>
#include <cstdint>

#define B_   1024
#define L_   50
#define D_   256
#define D2_  512
#define DEG_ 12
#define BL_  (B_ * L_)   // 51200
#define GM_  40000       // number of graph nodes

// ---------------- scratch (device globals; no allocations allowed) ----------
__device__ __align__(16) float g_temb[B_ * D_];
__device__ __align__(16) float g_t2[B_ * D_];
__device__ float g_alpha[B_];
__device__ __align__(16) float g_gemb[(size_t)GM_ * D_];          // graph_embs fp32
__device__ __align__(16) __nv_bfloat16 g_a_hi[(size_t)GM_ * D_];  // graph_embs hi
__device__ __align__(16) __nv_bfloat16 g_a_lo[(size_t)GM_ * D_];  // graph_embs lo
__device__ __align__(16) float g_G1[(size_t)GM_ * D_];            // graph_embs @ W1
__device__ __align__(16) __nv_bfloat16 g_w1t_hi[D_ * D_];         // W1^T hi [n][k]
__device__ __align__(16) __nv_bfloat16 g_w1t_lo[D_ * D_];         // W1^T lo [n][k]
__device__ float g_scores[BL_];
__device__ float g_attn[BL_];

// ---------------- small helpers ---------------------------------------------
__device__ __forceinline__ float wredsum(float v) {
#pragma unroll
    for (int o = 16; o > 0; o >>= 1) v += __shfl_xor_sync(0xFFFFFFFFu, v, o);
    return v;
}
__device__ __forceinline__ float wredmax(float v) {
#pragma unroll
    for (int o = 16; o > 0; o >>= 1) v = fmaxf(v, __shfl_xor_sync(0xFFFFFFFFu, v, o));
    return v;
}
__device__ __forceinline__ uint32_t smem_u32(const void* p) {
    uint32_t a;
    asm("{ .reg .u64 t; cvta.to.shared.u64 t, %1; cvt.u32.u64 %0, t; }" : "=r"(a) : "l"(p));
    return a;
}
__device__ __forceinline__ uint32_t pk2(__nv_bfloat16 a, __nv_bfloat16 b) {
    __nv_bfloat162 p(a, b);
    return *(uint32_t*)&p;
}
__device__ __forceinline__ void cpa16(uint32_t dst, const void* src) {
    asm volatile("cp.async.cg.shared.global [%0], [%1], 16;" :: "r"(dst), "l"(src));
}
__device__ __forceinline__ void ldsm4(uint32_t* r, uint32_t addr) {
    asm volatile("ldmatrix.sync.aligned.m8n8.x4.shared.b16 {%0,%1,%2,%3}, [%4];"
                 : "=r"(r[0]), "=r"(r[1]), "=r"(r[2]), "=r"(r[3]) : "r"(addr));
}
__device__ __forceinline__ void mma_bf16(float* c, const uint32_t* a, uint32_t b0, uint32_t b1) {
    asm volatile(
        "mma.sync.aligned.m16n8k16.row.col.f32.bf16.bf16.f32 "
        "{%0,%1,%2,%3}, {%4,%5,%6,%7}, {%8,%9}, {%0,%1,%2,%3};"
        : "+f"(c[0]), "+f"(c[1]), "+f"(c[2]), "+f"(c[3])
        : "r"(a[0]), "r"(a[1]), "r"(a[2]), "r"(a[3]), "r"(b0), "r"(b1));
}

// ---------------- K1: temb = tgt @ wfw^T + wfb ------------------------------
__global__ void k_temb(const float* __restrict__ tgt, const float* __restrict__ wfw,
                       const float* __restrict__ wfb) {
    __shared__ __align__(16) float ts[8][512];
    int tid = threadIdx.x;
    int b0 = blockIdx.x * 8;
#pragma unroll
    for (int ii = 0; ii < 4; ii++) {
        int f = ii * 256 + tid;
        int r = f >> 7, k4 = (f & 127) << 2;
        *(float4*)&ts[r][k4] = *(const float4*)&tgt[(size_t)(b0 + r) * D2_ + k4];
    }
    __syncthreads();
    int w = tid >> 5, lane = tid & 31;
#pragma unroll
    for (int dd = 0; dd < 4; dd++) {
        int d = blockIdx.y * 32 + w * 4 + dd;
        float acc[8];
#pragma unroll
        for (int r = 0; r < 8; r++) acc[r] = 0.f;
#pragma unroll
        for (int kc = 0; kc < 4; kc++) {
            int k = kc * 128 + lane * 4;
            float4 wv = *(const float4*)&wfw[(size_t)d * D2_ + k];
#pragma unroll
            for (int r = 0; r < 8; r++) {
                float4 tv = *(const float4*)&ts[r][k];
                acc[r] += wv.x * tv.x + wv.y * tv.y + wv.z * tv.z + wv.w * tv.w;
            }
        }
        float bias = wfb[d];
        float outv = 0.f;
#pragma unroll
        for (int r = 0; r < 8; r++) {
            float s = wredsum(acc[r]);
            if (lane == r) outv = s + bias;
        }
        if (lane < 8) g_temb[(size_t)(b0 + lane) * D_ + d] = outv;
    }
}

// ---------------- K2: t2 = temb @ w2 + bias ---------------------------------
__global__ void k_t2(const float* __restrict__ w2, const float* __restrict__ bias) {
    __shared__ __align__(16) float ts[16][256];
    int tid = threadIdx.x;
    int b0 = blockIdx.x * 16;
#pragma unroll
    for (int ii = 0; ii < 4; ii++) {
        int f = ii * 256 + tid;
        int r = f >> 6, k4 = (f & 63) << 2;
        *(float4*)&ts[r][k4] = *(const float4*)&g_temb[(size_t)(b0 + r) * D_ + k4];
    }
    __syncthreads();
    int rg = tid >> 6, nc = tid & 63;
    float acc[4][4];
#pragma unroll
    for (int i = 0; i < 4; i++)
#pragma unroll
        for (int j = 0; j < 4; j++) acc[i][j] = 0.f;
#pragma unroll 4
    for (int k = 0; k < 256; k++) {
        float4 wv = *(const float4*)&w2[(size_t)k * D_ + nc * 4];
#pragma unroll
        for (int i = 0; i < 4; i++) {
            float a = ts[rg * 4 + i][k];
            acc[i][0] += a * wv.x;
            acc[i][1] += a * wv.y;
            acc[i][2] += a * wv.z;
            acc[i][3] += a * wv.w;
        }
    }
    float4 bv = *(const float4*)&bias[nc * 4];
#pragma unroll
    for (int i = 0; i < 4; i++) {
        float4 o;
        o.x = acc[i][0] + bv.x;
        o.y = acc[i][1] + bv.y;
        o.z = acc[i][2] + bv.z;
        o.w = acc[i][3] + bv.w;
        *(float4*)&g_t2[(size_t)(b0 + rg * 4 + i) * D_ + nc * 4] = o;
    }
}

// ---------------- K3: alpha -------------------------------------------------
__global__ void k_alpha(const float* __restrict__ aw, const float* __restrict__ ab) {
    int lane = threadIdx.x & 31;
    int b = blockIdx.x * 8 + (threadIdx.x >> 5);
    const float* t = g_temb + (size_t)b * D_ + lane * 8;
    float s = 0.f;
#pragma unroll
    for (int j = 0; j < 8; j++) s += t[j] * aw[lane * 8 + j];
    s = wredsum(s);
    if (lane == 0) {
        float x = s + ab[0];
        float a = 1.f / (1.f + expf(-x)) + 1.f;
        if (a == 1.f) a = 1.00001f;
        g_alpha[b] = a;
    }
}

// ---------------- K4: W1 transpose + bf16 hi/lo split -----------------------
__global__ void k_prepw(const float* __restrict__ w1) {
    int f = blockIdx.x * 256 + threadIdx.x;   // 65536 total
    float a = w1[f];
    int k = f >> 8, n = f & 255;
    __nv_bfloat16 h = __float2bfloat16(a);
    float lo = a - __bfloat162float(h);
    g_w1t_hi[n * 256 + k] = h;
    g_w1t_lo[n * 256 + k] = __float2bfloat16(lo);
}

// ---------------- K5: graph conv over all 40000 nodes + bf16 split ----------
__global__ void k_gconv(const float* __restrict__ emb, const int* __restrict__ cols,
                        const float* __restrict__ vals) {
    int tid = threadIdx.x;
    int node = blockIdx.x * 4 + (tid >> 6);
    int d4 = (tid & 63) << 2;
    float4 h = *(const float4*)&emb[(size_t)node * D_ + d4];
    int base = node * DEG_;
#pragma unroll
    for (int j = 0; j < DEG_; j++) {
        int c = __ldg(&cols[base + j]);
        float v = __ldg(&vals[base + j]);
        float4 e = *(const float4*)&emb[(size_t)c * D_ + d4];
        h.x += v * e.x;
        h.y += v * e.y;
        h.z += v * e.z;
        h.w += v * e.w;
    }
    h.x *= 0.5f; h.y *= 0.5f; h.z *= 0.5f; h.w *= 0.5f;
    size_t off = (size_t)node * D_ + d4;
    *(float4*)&g_gemb[off] = h;
    __nv_bfloat16 h0 = __float2bfloat16(h.x), h1 = __float2bfloat16(h.y);
    __nv_bfloat16 h2 = __float2bfloat16(h.z), h3 = __float2bfloat16(h.w);
    __nv_bfloat16 l0 = __float2bfloat16(h.x - __bfloat162float(h0));
    __nv_bfloat16 l1 = __float2bfloat16(h.y - __bfloat162float(h1));
    __nv_bfloat16 l2 = __float2bfloat16(h.z - __bfloat162float(h2));
    __nv_bfloat16 l3 = __float2bfloat16(h.w - __bfloat162float(h3));
    *(uint2*)&g_a_hi[off] = make_uint2(pk2(h0, h1), pk2(h2, h3));
    *(uint2*)&g_a_lo[off] = make_uint2(pk2(l0, l1), pk2(l2, l3));
}

// ---------------- K6: G1 = graph_embs @ W1 (mma.sync bf16 3-split) ----------
// CTA tile 128m x 128n, K in 4 chunks of 64, cp.async double-buffered.
// smem per buf: A_hi 16KB | A_lo 16KB | B_hi 16KB | B_lo 16KB = 64KB; 2 bufs.
#define GEMM_SMEM 131072

__device__ __forceinline__ void load_chunk(uint32_t sb, int tid, int row0, int n0, int kc) {
#pragma unroll
    for (int i = 0; i < 4; i++) {
        int idx = tid + i * 256;
        int r = idx >> 3, gg = idx & 7;
        uint32_t soff = (uint32_t)(r * 128 + ((gg ^ (r & 7)) << 4));
        int ar = min(row0 + r, GM_ - 1);
        size_t abase = (size_t)ar * 256 + kc * 64 + gg * 8;
        cpa16(sb + soff,          g_a_hi + abase);
        cpa16(sb + 16384 + soff,  g_a_lo + abase);
        size_t bbase = (size_t)(n0 + r) * 256 + kc * 64 + gg * 8;
        cpa16(sb + 32768 + soff,  g_w1t_hi + bbase);
        cpa16(sb + 49152 + soff,  g_w1t_lo + bbase);
    }
    asm volatile("cp.async.commit_group;" ::: "memory");
}

__global__ __launch_bounds__(256, 1) void k_gemm2() {
    extern __shared__ char sm[];
    uint32_t sbase = smem_u32(sm);
    int tid = threadIdx.x, lane = tid & 31, w = tid >> 5;
    int wm = w & 1, wn = w >> 1;                 // 2x4 warp grid: 64m x 32n per warp
    int row0 = blockIdx.x * 128, n0 = blockIdx.y * 128;
    int quad = lane >> 3, ri = lane & 7;
    int arow_b = wm * 64 + ((quad & 1) << 3) + ri;   // + mt*16
    int brow_b = wn * 32 + ((quad & 1) << 3) + ri;   // + pt*16
    int gsel = quad >> 1;                             // + ks*2

    float acc[4][4][4];
#pragma unroll
    for (int i = 0; i < 4; i++)
#pragma unroll
        for (int j = 0; j < 4; j++)
#pragma unroll
            for (int q = 0; q < 4; q++) acc[i][j][q] = 0.f;

    load_chunk(sbase, tid, row0, n0, 0);

#pragma unroll
    for (int kc = 0; kc < 4; kc++) {
        uint32_t sb = sbase + (kc & 1) * 65536;
        if (kc < 3) {
            load_chunk(sbase + ((kc + 1) & 1) * 65536, tid, row0, n0, kc + 1);
            asm volatile("cp.async.wait_group 1;" ::: "memory");
        } else {
            asm volatile("cp.async.wait_group 0;" ::: "memory");
        }
        __syncthreads();
#pragma unroll
        for (int ks = 0; ks < 4; ks++) {
            uint32_t ah[4][4], al[4][4], bh[2][4], bl[2][4];
            int gx = ((ks * 2 + gsel) ^ ri) << 4;
#pragma unroll
            for (int mt = 0; mt < 4; mt++) {
                uint32_t off = (uint32_t)((arow_b + mt * 16) * 128 + gx);
                ldsm4(ah[mt], sb + off);
                ldsm4(al[mt], sb + 16384 + off);
            }
#pragma unroll
            for (int pt = 0; pt < 2; pt++) {
                uint32_t off = (uint32_t)((brow_b + pt * 16) * 128 + gx);
                ldsm4(bh[pt], sb + 32768 + off);
                ldsm4(bl[pt], sb + 49152 + off);
            }
#pragma unroll
            for (int mt = 0; mt < 4; mt++) {
#pragma unroll
                for (int nt = 0; nt < 4; nt++) {
                    uint32_t b0h = bh[nt >> 1][nt & 1], b1h = bh[nt >> 1][(nt & 1) + 2];
                    uint32_t b0l = bl[nt >> 1][nt & 1], b1l = bl[nt >> 1][(nt & 1) + 2];
                    mma_bf16(acc[mt][nt], ah[mt], b0h, b1h);
                    mma_bf16(acc[mt][nt], ah[mt], b0l, b1l);
                    mma_bf16(acc[mt][nt], al[mt], b0h, b1h);
                }
            }
        }
        __syncthreads();
    }

    // epilogue: accumulators -> g_G1
    int mrb = row0 + wm * 64 + (lane >> 2);
    int ncb = n0 + wn * 32 + (lane & 3) * 2;
#pragma unroll
    for (int mt = 0; mt < 4; mt++) {
#pragma unroll
        for (int nt = 0; nt < 4; nt++) {
            int m = mrb + mt * 16;
            int n = ncb + nt * 8;
            if (m < GM_)
                *(float2*)&g_G1[(size_t)m * D_ + n] =
                    make_float2(acc[mt][nt][0], acc[mt][nt][1]);
            if (m + 8 < GM_)
                *(float2*)&g_G1[(size_t)(m + 8) * D_ + n] =
                    make_float2(acc[mt][nt][2], acc[mt][nt][3]);
        }
    }
}

// ---------------- K7: scores = relu(G1[item] + t2[b]) . w0 ------------------
__global__ void k_scores_epi(const int* __restrict__ items, const float* __restrict__ w0) {
    int lane = threadIdx.x & 31;
    int row = blockIdx.x * 8 + (threadIdx.x >> 5);
    int it = __ldg(&items[row]);
    int b = row / L_;
    const float* g = g_G1 + (size_t)it * D_ + lane * 8;
    const float* t = g_t2 + (size_t)b * D_ + lane * 8;
    float4 g0 = *(const float4*)g, g1 = *(const float4*)(g + 4);
    float4 t0 = *(const float4*)t, t1 = *(const float4*)(t + 4);
    float4 w0a = *(const float4*)&w0[lane * 8];
    float4 w0b = *(const float4*)&w0[lane * 8 + 4];
    float acc = fmaxf(g0.x + t0.x, 0.f) * w0a.x + fmaxf(g0.y + t0.y, 0.f) * w0a.y +
                fmaxf(g0.z + t0.z, 0.f) * w0a.z + fmaxf(g0.w + t0.w, 0.f) * w0a.w +
                fmaxf(g1.x + t1.x, 0.f) * w0b.x + fmaxf(g1.y + t1.y, 0.f) * w0b.y +
                fmaxf(g1.z + t1.z, 0.f) * w0b.z + fmaxf(g1.w + t1.w, 0.f) * w0b.w;
    acc = wredsum(acc);
    if (lane == 0) g_scores[row] = acc;
}

// ---------------- K8: entmax-bisect over L=50, one warp per batch row -------
__device__ __forceinline__ float pfun(float z, float inv) {
    z = fmaxf(z, 0.f);
    return powf(z, inv);
}

__global__ void k_entmax() {
    int lane = threadIdx.x & 31;
    int b = blockIdx.x * 8 + (threadIdx.x >> 5);
    float alpha = g_alpha[b];
    float am1 = alpha - 1.f;
    float inv = 1.f / am1;
    float Xa0 = g_scores[b * L_ + lane] * am1;
    float Xa1 = (lane < L_ - 32) ? g_scores[b * L_ + 32 + lane] * am1 : -CUDART_INF_F;

    float m = wredmax(fmaxf(Xa0, Xa1));
    float tau_lo = m - 1.f;
    float tau_hi = m - powf(1.f / (float)L_, am1);
    float f_lo = wredsum(pfun(Xa0 - tau_lo, inv) + pfun(Xa1 - tau_lo, inv)) - 1.f;

    float dm = tau_hi - tau_lo;
    float tau_m = tau_lo;
    for (int it = 0; it < 50; it++) {
        dm *= 0.5f;
        tau_m = tau_lo + dm;
        float fm = wredsum(pfun(Xa0 - tau_m, inv) + pfun(Xa1 - tau_m, inv)) - 1.f;
        if (fm * f_lo >= 0.f) tau_lo = tau_m;
    }
    float p0 = pfun(Xa0 - tau_m, inv);
    float p1 = pfun(Xa1 - tau_m, inv);
    float s = wredsum(p0 + p1);
    g_attn[b * L_ + lane] = p0 / s;
    if (lane < L_ - 32) g_attn[b * L_ + 32 + lane] = p1 / s;
}

// ---------------- K9: c = attn^T gather(graph_embs); selu; normalize --------
__global__ void k_out(const int* __restrict__ items, float* __restrict__ out) {
    __shared__ float as[64];
    __shared__ int its[64];
    __shared__ float rs[8];
    int tid = threadIdx.x;
    int b = blockIdx.x;
    if (tid < L_) {
        as[tid] = g_attn[b * L_ + tid];
        its[tid] = items[b * L_ + tid];
    }
    __syncthreads();
    float acc = 0.f;
#pragma unroll
    for (int l = 0; l < L_; l++) acc += as[l] * g_gemb[(size_t)its[l] * D_ + tid];
    const float SC = 1.0507009873554805f;
    const float AL = 1.6732632423543772f;
    float v = acc > 0.f ? SC * acc : SC * AL * expm1f(acc);
    float sq = wredsum(v * v);
    if ((tid & 31) == 0) rs[tid >> 5] = sq;
    __syncthreads();
    if (tid < 32) {
        float t = (tid < 8) ? rs[tid] : 0.f;
        t = wredsum(t);
        if (tid == 0) rs[0] = t;
    }
    __syncthreads();
    out[(size_t)b * D_ + tid] = v / sqrtf(rs[0]);
}

// ---------------- launch ------------------------------------------------------
extern "C" void kernel_launch(void* const* d_in, const int* in_sizes, int n_in,
                              void* d_out, int out_size) {
    const int* items = (const int*)d_in[0];
    const float* tgt = (const float*)d_in[3];
    const float* emb = (const float*)d_in[4];
    const int* acols = (const int*)d_in[6];
    const float* avals = (const float*)d_in[7];
    const float* wfw = (const float*)d_in[8];
    const float* wfb = (const float*)d_in[9];
    const float* aww = (const float*)d_in[10];
    const float* awb = (const float*)d_in[11];
    const float* w0 = (const float*)d_in[12];
    const float* w1 = (const float*)d_in[13];
    const float* w2 = (const float*)d_in[14];
    const float* abias = (const float*)d_in[15];
    float* out = (float*)d_out;

    cudaFuncSetAttribute(k_gemm2, cudaFuncAttributeMaxDynamicSharedMemorySize, GEMM_SMEM);

    k_prepw<<<256, 256>>>(w1);
    k_temb<<<dim3(128, 8), 256>>>(tgt, wfw, wfb);
    k_t2<<<64, 256>>>(w2, abias);
    k_alpha<<<128, 256>>>(aww, awb);
    k_gconv<<<GM_ / 4, 256>>>(emb, acols, avals);
    k_gemm2<<<dim3((GM_ + 127) / 128, 2), 256, GEMM_SMEM>>>();
    k_scores_epi<<<BL_ / 8, 256>>>(items, w0);
    k_entmax<<<128, 256>>>();
    k_out<<<B_, 256>>>(items, out);
}